// round 6
// baseline (speedup 1.0000x reference)
#include <cuda_runtime.h>

#define NB 8192
#define NFLD 64
#define DDIM 128

typedef unsigned long long u64;

// Scratch (device globals — no allocation allowed)
__device__ float g_S[(size_t)NB * NFLD * NFLD];   // S[b][i][j]  (128 MB)
__device__ float g_KwT[DDIM * DDIM];              // KwT[d][e] = K_w[e][d]
__device__ float g_QwT[DDIM * DDIM];              // QwT[d][e] = Q_w[e][d]

// ---------------- f32x2 packed-FMA helpers (sm_100+) ----------------
__device__ __forceinline__ u64 pack2(float x) {
    u64 r;
    asm("mov.b64 %0, {%1, %1};" : "=l"(r) : "f"(x));
    return r;
}
__device__ __forceinline__ void fma2(u64& d, u64 a, u64 b) {
    asm("fma.rn.f32x2 %0, %1, %2, %0;" : "+l"(d) : "l"(a), "l"(b));
}
__device__ __forceinline__ float2 unpack2(u64 v) {
    float lo, hi;
    asm("mov.b64 {%0, %1}, %2;" : "=f"(lo), "=f"(hi) : "l"(v));
    return make_float2(lo, hi);
}

// ---------------- Kernel 0: transpose weights ----------------
__global__ void transpose_wk(const float* __restrict__ Kw, const float* __restrict__ Qw) {
    int idx = blockIdx.x * 256 + threadIdx.x;
    if (idx < DDIM * DDIM) {
        int e = idx >> 7;
        int d = idx & 127;
        g_KwT[d * DDIM + e] = Kw[idx];
        g_QwT[d * DDIM + e] = Qw[idx];
    }
}

// ---------------- Kernel 1: per-batch Kf and S ----------------
// smem: Fs[64][129] (F_b, padded), Kft[128][68] (Kf transposed, e-major),
//       Bs[32][128] (KwT chunk)
#define FS_LD 129
#define KFT_LD 68
#define K1_SMEM ((64 * FS_LD + 128 * KFT_LD + 32 * DDIM) * sizeof(float))

__global__ void __launch_bounds__(256, 2) k1_score(const float* __restrict__ F) {
    extern __shared__ float sm[];
    float* Fs  = sm;                   // 64*129  = 8256 floats
    float* Kft = sm + 64 * FS_LD;      // 128*68  = 8704 floats
    float* Bs  = Kft + 128 * KFT_LD;   // 32*128  = 4096 floats

    const int b   = blockIdx.x;
    const int tid = threadIdx.x;
    const int ty  = tid >> 4;   // 0..15
    const int tx  = tid & 15;   // 0..15
    const int arow = ty * 4;    // j / i base row

    // ---- stage F_b [64][128] into Fs (padded rows) ----
    {
        const float4* F4 = reinterpret_cast<const float4*>(F) + (size_t)b * (NFLD * DDIM / 4);
        #pragma unroll
        for (int it = 0; it < 8; it++) {
            int x = tid + it * 256;           // 0..2047
            float4 v = F4[x];
            int j  = x >> 5;                  // 0..63
            int dq = (x & 31) << 2;           // 0..124
            float* p = Fs + j * FS_LD + dq;
            p[0] = v.x; p[1] = v.y; p[2] = v.z; p[3] = v.w;
        }
    }

    // ---- Kf[j][e] = sum_d Fs[j][d] * KwT[d][e] ----
    // thread tile: 4 j-rows (arow..arow+3) x 8 e-cols (tx*4..+3, 64+tx*4..+3)
    u64 acc[4][4];
    #pragma unroll
    for (int r = 0; r < 4; r++) {
        acc[r][0] = 0ull; acc[r][1] = 0ull; acc[r][2] = 0ull; acc[r][3] = 0ull;
    }

    #pragma unroll 1
    for (int ck = 0; ck < 4; ck++) {
        __syncthreads();   // prior chunk compute done (and Fs staged, first iter)
        {
            const float4* KT4 = reinterpret_cast<const float4*>(g_KwT) + ck * (32 * DDIM / 4);
            #pragma unroll
            for (int it = 0; it < 4; it++)
                reinterpret_cast<float4*>(Bs)[tid + it * 256] = KT4[tid + it * 256];
        }
        __syncthreads();
        const int d0 = ck * 32;
        #pragma unroll 8
        for (int dd = 0; dd < 32; dd++) {
            u64 a0 = pack2(Fs[(arow + 0) * FS_LD + d0 + dd]);
            u64 a1 = pack2(Fs[(arow + 1) * FS_LD + d0 + dd]);
            u64 a2 = pack2(Fs[(arow + 2) * FS_LD + d0 + dd]);
            u64 a3 = pack2(Fs[(arow + 3) * FS_LD + d0 + dd]);
            ulonglong2 b0 = *reinterpret_cast<const ulonglong2*>(Bs + dd * DDIM + tx * 4);
            ulonglong2 b1 = *reinterpret_cast<const ulonglong2*>(Bs + dd * DDIM + 64 + tx * 4);
            fma2(acc[0][0], a0, b0.x); fma2(acc[0][1], a0, b0.y);
            fma2(acc[0][2], a0, b1.x); fma2(acc[0][3], a0, b1.y);
            fma2(acc[1][0], a1, b0.x); fma2(acc[1][1], a1, b0.y);
            fma2(acc[1][2], a1, b1.x); fma2(acc[1][3], a1, b1.y);
            fma2(acc[2][0], a2, b0.x); fma2(acc[2][1], a2, b0.y);
            fma2(acc[2][2], a2, b1.x); fma2(acc[2][3], a2, b1.y);
            fma2(acc[3][0], a3, b0.x); fma2(acc[3][1], a3, b0.y);
            fma2(acc[3][2], a3, b1.x); fma2(acc[3][3], a3, b1.y);
        }
    }

    // ---- write Kf transposed: Kft[e][j] ----
    #pragma unroll
    for (int r = 0; r < 4; r++) {
        int j = arow + r;
        float2 p0 = unpack2(acc[r][0]);
        float2 p1 = unpack2(acc[r][1]);
        float2 p2 = unpack2(acc[r][2]);
        float2 p3 = unpack2(acc[r][3]);
        Kft[(tx * 4 + 0) * KFT_LD + j] = p0.x;
        Kft[(tx * 4 + 1) * KFT_LD + j] = p0.y;
        Kft[(tx * 4 + 2) * KFT_LD + j] = p1.x;
        Kft[(tx * 4 + 3) * KFT_LD + j] = p1.y;
        Kft[(64 + tx * 4 + 0) * KFT_LD + j] = p2.x;
        Kft[(64 + tx * 4 + 1) * KFT_LD + j] = p2.y;
        Kft[(64 + tx * 4 + 2) * KFT_LD + j] = p3.x;
        Kft[(64 + tx * 4 + 3) * KFT_LD + j] = p3.y;
    }
    __syncthreads();

    // ---- S[i][j] = sum_e Fs[i][e] * Kft[e][j]  (4 i x 4 j per thread) ----
    u64 s[4][2];
    #pragma unroll
    for (int r = 0; r < 4; r++) { s[r][0] = 0ull; s[r][1] = 0ull; }

    #pragma unroll 8
    for (int e = 0; e < DDIM; e++) {
        u64 a0 = pack2(Fs[(arow + 0) * FS_LD + e]);
        u64 a1 = pack2(Fs[(arow + 1) * FS_LD + e]);
        u64 a2 = pack2(Fs[(arow + 2) * FS_LD + e]);
        u64 a3 = pack2(Fs[(arow + 3) * FS_LD + e]);
        ulonglong2 bb = *reinterpret_cast<const ulonglong2*>(Kft + e * KFT_LD + tx * 4);
        fma2(s[0][0], a0, bb.x); fma2(s[0][1], a0, bb.y);
        fma2(s[1][0], a1, bb.x); fma2(s[1][1], a1, bb.y);
        fma2(s[2][0], a2, bb.x); fma2(s[2][1], a2, bb.y);
        fma2(s[3][0], a3, bb.x); fma2(s[3][1], a3, bb.y);
    }

    // ---- store S[b][i][j] ----
    float* So = g_S + (size_t)b * NFLD * NFLD;
    #pragma unroll
    for (int r = 0; r < 4; r++) {
        float2 q0 = unpack2(s[r][0]);
        float2 q1 = unpack2(s[r][1]);
        *reinterpret_cast<float4*>(So + (size_t)(arow + r) * NFLD + tx * 4) =
            make_float4(q0.x, q0.y, q1.x, q1.y);
    }
}

// ---------------- Kernel 2: out[:,i,:] = S[:,i,:]@W[i] + F[:,i,:]@QwT ----------------
// grid: (64 b-tiles of 128, 64 i). 128x128 output tile, 8x8 per thread.
// smem: As[128][65] (A chunk, K<=64), Bs[64][128] (B chunk, k-major)
#define AS_LD 65
#define K2_SMEM ((128 * AS_LD + 64 * DDIM) * sizeof(float))

__global__ void __launch_bounds__(256, 2) k2_out(
    const float* __restrict__ F, const float* __restrict__ W, float* __restrict__ out)
{
    extern __shared__ float sm[];
    float* As = sm;                 // 128*65 = 8320 floats
    float* Bs = sm + 128 * AS_LD;   // 64*128 = 8192 floats

    const int i   = blockIdx.y;
    const int b0  = blockIdx.x * 128;
    const int tid = threadIdx.x;
    const int ty  = tid >> 4;       // 0..15
    const int tx  = tid & 15;       // 0..15
    const int r0  = ty * 8;         // row base (batch within tile)

    u64 acc[8][4];
    #pragma unroll
    for (int rr = 0; rr < 8; rr++) {
        acc[rr][0] = 0ull; acc[rr][1] = 0ull; acc[rr][2] = 0ull; acc[rr][3] = 0ull;
    }

    // ===== Phase A: S[b0:b0+128, i, :] @ W[i]  (K = 64) =====
    {
        const float* Sbase = g_S + ((size_t)b0 * NFLD + i) * NFLD;
        #pragma unroll
        for (int it = 0; it < 8; it++) {
            int x = tid + it * 256;          // 0..2047
            int u = x >> 4;                  // 0..127
            int q = (x & 15) << 2;           // 0..60
            float4 v = *reinterpret_cast<const float4*>(Sbase + (size_t)u * (NFLD * NFLD) + q);
            float* p = As + u * AS_LD + q;
            p[0] = v.x; p[1] = v.y; p[2] = v.z; p[3] = v.w;
        }
        const float4* W4 = reinterpret_cast<const float4*>(W) + (size_t)i * (NFLD * DDIM / 4);
        #pragma unroll
        for (int it = 0; it < 8; it++)
            reinterpret_cast<float4*>(Bs)[tid + it * 256] = W4[tid + it * 256];
    }
    __syncthreads();
    #pragma unroll 4
    for (int k = 0; k < 64; k++) {
        u64 a2[8];
        #pragma unroll
        for (int rr = 0; rr < 8; rr++) a2[rr] = pack2(As[(r0 + rr) * AS_LD + k]);
        ulonglong2 bA = *reinterpret_cast<const ulonglong2*>(Bs + k * DDIM + tx * 4);
        ulonglong2 bB = *reinterpret_cast<const ulonglong2*>(Bs + k * DDIM + 64 + tx * 4);
        #pragma unroll
        for (int rr = 0; rr < 8; rr++) {
            fma2(acc[rr][0], a2[rr], bA.x);
            fma2(acc[rr][1], a2[rr], bA.y);
            fma2(acc[rr][2], a2[rr], bB.x);
            fma2(acc[rr][3], a2[rr], bB.y);
        }
    }

    // ===== Phase B: F[b0:b0+128, i, :] @ QwT  (K = 128, two 64-chunks) =====
    #pragma unroll 1
    for (int kc = 0; kc < 2; kc++) {
        __syncthreads();   // previous compute done before overwriting As/Bs
        const float* Fbase = F + ((size_t)b0 * NFLD + i) * DDIM + kc * 64;
        #pragma unroll
        for (int it = 0; it < 8; it++) {
            int x = tid + it * 256;
            int u = x >> 4;
            int q = (x & 15) << 2;
            float4 v = *reinterpret_cast<const float4*>(Fbase + (size_t)u * (NFLD * DDIM) + q);
            float* p = As + u * AS_LD + q;
            p[0] = v.x; p[1] = v.y; p[2] = v.z; p[3] = v.w;
        }
        const float4* Q4 = reinterpret_cast<const float4*>(g_QwT) + kc * (64 * DDIM / 4);
        #pragma unroll
        for (int it = 0; it < 8; it++)
            reinterpret_cast<float4*>(Bs)[tid + it * 256] = Q4[tid + it * 256];
        __syncthreads();
        #pragma unroll 4
        for (int k = 0; k < 64; k++) {
            u64 a2[8];
            #pragma unroll
            for (int rr = 0; rr < 8; rr++) a2[rr] = pack2(As[(r0 + rr) * AS_LD + k]);
            ulonglong2 bA = *reinterpret_cast<const ulonglong2*>(Bs + k * DDIM + tx * 4);
            ulonglong2 bB = *reinterpret_cast<const ulonglong2*>(Bs + k * DDIM + 64 + tx * 4);
            #pragma unroll
            for (int rr = 0; rr < 8; rr++) {
                fma2(acc[rr][0], a2[rr], bA.x);
                fma2(acc[rr][1], a2[rr], bA.y);
                fma2(acc[rr][2], a2[rr], bB.x);
                fma2(acc[rr][3], a2[rr], bB.y);
            }
        }
    }

    // ===== epilogue: out[b0+u, i, :] =====
    #pragma unroll
    for (int rr = 0; rr < 8; rr++) {
        int u = r0 + rr;
        float2 q0 = unpack2(acc[rr][0]);
        float2 q1 = unpack2(acc[rr][1]);
        float2 q2 = unpack2(acc[rr][2]);
        float2 q3 = unpack2(acc[rr][3]);
        float* ob = out + ((size_t)(b0 + u) * NFLD + i) * DDIM;
        *reinterpret_cast<float4*>(ob + tx * 4)      = make_float4(q0.x, q0.y, q1.x, q1.y);
        *reinterpret_cast<float4*>(ob + 64 + tx * 4) = make_float4(q2.x, q2.y, q3.x, q3.y);
    }
}

// ---------------- launch ----------------
extern "C" void kernel_launch(void* const* d_in, const int* in_sizes, int n_in,
                              void* d_out, int out_size) {
    const float* F  = (const float*)d_in[0];
    const float* W  = (const float*)d_in[1];
    const float* Kw = (const float*)d_in[2];
    const float* Qw = (const float*)d_in[3];
    float* out = (float*)d_out;

    // >48KB dynamic smem requires opt-in (idempotent; also runs in the
    // correctness call before capture, so the attribute is already set).
    cudaFuncSetAttribute(k1_score, cudaFuncAttributeMaxDynamicSharedMemorySize, (int)K1_SMEM);
    cudaFuncSetAttribute(k2_out,   cudaFuncAttributeMaxDynamicSharedMemorySize, (int)K2_SMEM);

    transpose_wk<<<64, 256>>>(Kw, Qw);
    k1_score<<<NB, 256, K1_SMEM>>>(F);
    dim3 g2(NB / 128, NFLD);
    k2_out<<<g2, 256, K2_SMEM>>>(F, W, out);
}

// round 7
// speedup vs baseline: 2.7306x; 2.7306x over previous
#include <cuda_runtime.h>
#include <cstdint>

#define NB 8192
#define NFLD 64
#define DDIM 128

// Scratch (device global — no allocation allowed)
__device__ float g_S[(size_t)NB * NFLD * NFLD];   // S[b][i][j]  (128 MB)

// ---------------- tf32 helpers ----------------
__device__ __forceinline__ float f2tf(float f) {
    unsigned u;
    asm("cvt.rna.tf32.f32 %0, %1;" : "=r"(u) : "f"(f));
    return __uint_as_float(u);
}
__device__ __forceinline__ float4 f2tf4(float4 v) {
    return make_float4(f2tf(v.x), f2tf(v.y), f2tf(v.z), f2tf(v.w));
}
__device__ __forceinline__ unsigned fb(float f) { return __float_as_uint(f); }

// D += A*B : m16n8k8 tf32, A row-major frag (4 regs), B col-major frag (2 regs)
__device__ __forceinline__ void mma8(float* c, const unsigned* a, const unsigned* b) {
    asm("mma.sync.aligned.m16n8k8.row.col.f32.tf32.tf32.f32 "
        "{%0,%1,%2,%3},{%4,%5,%6,%7},{%8,%9},{%0,%1,%2,%3};"
        : "+f"(c[0]), "+f"(c[1]), "+f"(c[2]), "+f"(c[3])
        : "r"(a[0]), "r"(a[1]), "r"(a[2]), "r"(a[3]), "r"(b[0]), "r"(b[1]));
}

// ---------------- Kernel 1: per-batch Kf = F_b @ K_w^T, S = F_b @ Kf^T ----------------
#define FS_LD 132
#define KW_LD 36
#define KF_LD 132
#define SS_LD 68
#define K1_SMEM ((64 * FS_LD + 128 * KW_LD + 64 * KF_LD) * sizeof(float))

__global__ void __launch_bounds__(256, 2) k1_score(const float* __restrict__ F,
                                                   const float* __restrict__ Kw) {
    extern __shared__ float sm[];
    float* Fs  = sm;                    // 64 x 132 (tf32 F_b)
    float* Kws = sm + 64 * FS_LD;       // 128(e) x 36 (32-wide d-chunk of K_w)
    float* Kfs = Kws + 128 * KW_LD;     // 64 x 132 (tf32 Kf)
    float* Ss  = Kws;                   // reuse for S staging: 64 x 68 <= 128*36

    const int b    = blockIdx.x;
    const int tid  = threadIdx.x;
    const int lane = tid & 31;
    const int wid  = tid >> 5;
    const int wm   = wid >> 2;   // 0..1
    const int wn   = wid & 3;    // 0..3
    const int lr   = lane >> 2;  // 0..7
    const int lc   = lane & 3;   // 0..3

    // ---- stage F_b [64][128] -> Fs (tf32) ----
    {
        const float4* F4 = reinterpret_cast<const float4*>(F + (size_t)b * NFLD * DDIM);
        #pragma unroll
        for (int it = 0; it < 8; it++) {
            int x = tid + it * 256;            // 0..2047
            float4 v = f2tf4(F4[x]);
            int j = x >> 5, dq = (x & 31) << 2;
            *reinterpret_cast<float4*>(Fs + j * FS_LD + dq) = v;
        }
    }

    // ---- Kf[j][e] = sum_d F[j][d] * K_w[e][d]  (B = K_w as col-major frag) ----
    float accK[2][4][4];
    #pragma unroll
    for (int mt = 0; mt < 2; mt++)
        #pragma unroll
        for (int nt = 0; nt < 4; nt++)
            #pragma unroll
            for (int q = 0; q < 4; q++) accK[mt][nt][q] = 0.f;

    #pragma unroll 1
    for (int ck = 0; ck < 4; ck++) {
        __syncthreads();
        // stage K_w[:, ck*32 : ck*32+32] into Kws[e][dl] (tf32)
        #pragma unroll
        for (int it = 0; it < 4; it++) {
            int x = tid + it * 256;            // 0..1023
            int e = x >> 3, dq = (x & 7) << 2;
            float4 v = f2tf4(*reinterpret_cast<const float4*>(Kw + e * DDIM + ck * 32 + dq));
            *reinterpret_cast<float4*>(Kws + e * KW_LD + dq) = v;
        }
        __syncthreads();
        #pragma unroll
        for (int kk = 0; kk < 4; kk++) {
            const int c  = ck * 32 + kk * 8 + lc;   // global d for A
            const int kl = kk * 8 + lc;             // in-chunk d for B
            unsigned a[2][4];
            #pragma unroll
            for (int mt = 0; mt < 2; mt++) {
                int r = wm * 32 + mt * 16 + lr;
                a[mt][0] = fb(Fs[r * FS_LD + c]);
                a[mt][1] = fb(Fs[(r + 8) * FS_LD + c]);
                a[mt][2] = fb(Fs[r * FS_LD + c + 4]);
                a[mt][3] = fb(Fs[(r + 8) * FS_LD + c + 4]);
            }
            #pragma unroll
            for (int nt = 0; nt < 4; nt++) {
                int e = wn * 32 + nt * 8 + lr;
                unsigned bb[2];
                bb[0] = fb(Kws[e * KW_LD + kl]);
                bb[1] = fb(Kws[e * KW_LD + kl + 4]);
                #pragma unroll
                for (int mt = 0; mt < 2; mt++) mma8(accK[mt][nt], a[mt], bb);
            }
        }
    }

    // ---- write Kf -> Kfs (tf32), row-major [j][e] ----
    #pragma unroll
    for (int mt = 0; mt < 2; mt++) {
        int r = wm * 32 + mt * 16 + lr;
        #pragma unroll
        for (int nt = 0; nt < 4; nt++) {
            int e = wn * 32 + nt * 8 + 2 * lc;
            Kfs[r * KF_LD + e]           = f2tf(accK[mt][nt][0]);
            Kfs[r * KF_LD + e + 1]       = f2tf(accK[mt][nt][1]);
            Kfs[(r + 8) * KF_LD + e]     = f2tf(accK[mt][nt][2]);
            Kfs[(r + 8) * KF_LD + e + 1] = f2tf(accK[mt][nt][3]);
        }
    }
    __syncthreads();

    // ---- S[i][j] = sum_e F[i][e] * Kf[j][e]  (B = Kf as col-major frag) ----
    float accS[2][2][4];
    #pragma unroll
    for (int mt = 0; mt < 2; mt++)
        #pragma unroll
        for (int nt = 0; nt < 2; nt++)
            #pragma unroll
            for (int q = 0; q < 4; q++) accS[mt][nt][q] = 0.f;

    #pragma unroll
    for (int kk = 0; kk < 16; kk++) {
        const int c = kk * 8 + lc;
        unsigned a[2][4];
        #pragma unroll
        for (int mt = 0; mt < 2; mt++) {
            int r = wm * 32 + mt * 16 + lr;
            a[mt][0] = fb(Fs[r * FS_LD + c]);
            a[mt][1] = fb(Fs[(r + 8) * FS_LD + c]);
            a[mt][2] = fb(Fs[r * FS_LD + c + 4]);
            a[mt][3] = fb(Fs[(r + 8) * FS_LD + c + 4]);
        }
        #pragma unroll
        for (int nt = 0; nt < 2; nt++) {
            int j = wn * 16 + nt * 8 + lr;
            unsigned bb[2];
            bb[0] = fb(Kfs[j * KF_LD + c]);
            bb[1] = fb(Kfs[j * KF_LD + c + 4]);
            #pragma unroll
            for (int mt = 0; mt < 2; mt++) mma8(accS[mt][nt], a[mt], bb);
        }
    }

    // ---- stage S through smem, coalesced float4 store to g_S ----
    #pragma unroll
    for (int mt = 0; mt < 2; mt++) {
        int r = wm * 32 + mt * 16 + lr;
        #pragma unroll
        for (int nt = 0; nt < 2; nt++) {
            int j = wn * 16 + nt * 8 + 2 * lc;
            Ss[r * SS_LD + j]           = accS[mt][nt][0];
            Ss[r * SS_LD + j + 1]       = accS[mt][nt][1];
            Ss[(r + 8) * SS_LD + j]     = accS[mt][nt][2];
            Ss[(r + 8) * SS_LD + j + 1] = accS[mt][nt][3];
        }
    }
    __syncthreads();
    {
        float* So = g_S + (size_t)b * NFLD * NFLD;
        #pragma unroll
        for (int it = 0; it < 4; it++) {
            int x = tid + it * 256;            // 0..1023
            int i = x >> 4, jq = (x & 15) << 2;
            *reinterpret_cast<float4*>(So + i * NFLD + jq) =
                *reinterpret_cast<float4*>(Ss + i * SS_LD + jq);
        }
    }
}

// ---------------- Kernel 2: out[:,i,:] = S[:,i,:] @ W[i] + F[:,i,:] @ Q_w^T ----------------
#define AS_LD 68
#define BW_LD 132
#define BQ_LD 68
#define K2_BS_FLOATS 8704   // max(64*132 = 8448, 128*68 = 8704)
#define K2_SMEM ((128 * AS_LD + K2_BS_FLOATS) * sizeof(float))

__global__ void __launch_bounds__(256, 2) k2_out(const float* __restrict__ F,
                                                 const float* __restrict__ W,
                                                 const float* __restrict__ Qw,
                                                 float* __restrict__ out) {
    extern __shared__ float sm[];
    float* As = sm;                  // 128 x 68 (A chunk, tf32) / out staging
    float* Bs = sm + 128 * AS_LD;    // B chunk

    const int i    = blockIdx.y;
    const int b0   = blockIdx.x * 128;
    const int tid  = threadIdx.x;
    const int lane = tid & 31;
    const int wid  = tid >> 5;
    const int wm   = wid >> 2;   // 0..1 -> m 64 rows each
    const int wn   = wid & 3;    // 0..3 -> n 32 cols each
    const int lr   = lane >> 2;
    const int lc   = lane & 3;

    float acc[4][4][4];
    #pragma unroll
    for (int mt = 0; mt < 4; mt++)
        #pragma unroll
        for (int nt = 0; nt < 4; nt++)
            #pragma unroll
            for (int q = 0; q < 4; q++) acc[mt][nt][q] = 0.f;

    // ===== Phase A: S[b0:b0+128, i, :] @ W[i]   (K = 64) =====
    {
        const float* Sb = g_S + ((size_t)b0 * NFLD + i) * NFLD;
        #pragma unroll
        for (int it = 0; it < 8; it++) {
            int x = tid + it * 256;            // 0..2047
            int u = x >> 4, jq = (x & 15) << 2;
            float4 v = f2tf4(*reinterpret_cast<const float4*>(
                Sb + (size_t)u * NFLD * NFLD + jq));
            *reinterpret_cast<float4*>(As + u * AS_LD + jq) = v;
        }
        const float* Wi = W + (size_t)i * NFLD * DDIM;
        #pragma unroll
        for (int it = 0; it < 8; it++) {
            int x = tid + it * 256;            // 8192 floats, k(j)-major ld 132
            int j = x >> 5, dq = (x & 31) << 2;
            float4 v = f2tf4(*reinterpret_cast<const float4*>(Wi + j * DDIM + dq));
            *reinterpret_cast<float4*>(Bs + j * BW_LD + dq) = v;
        }
        __syncthreads();
        #pragma unroll
        for (int kk = 0; kk < 8; kk++) {
            const int k = kk * 8 + lc;
            unsigned a[4][4];
            #pragma unroll
            for (int mt = 0; mt < 4; mt++) {
                int r = wm * 64 + mt * 16 + lr;
                a[mt][0] = fb(As[r * AS_LD + k]);
                a[mt][1] = fb(As[(r + 8) * AS_LD + k]);
                a[mt][2] = fb(As[r * AS_LD + k + 4]);
                a[mt][3] = fb(As[(r + 8) * AS_LD + k + 4]);
            }
            #pragma unroll
            for (int nt = 0; nt < 4; nt++) {
                int n = wn * 32 + nt * 8 + lr;
                unsigned bb[2];
                bb[0] = fb(Bs[k * BW_LD + n]);
                bb[1] = fb(Bs[(k + 4) * BW_LD + n]);
                #pragma unroll
                for (int mt = 0; mt < 4; mt++) mma8(acc[mt][nt], a[mt], bb);
            }
        }
    }

    // ===== Phase B: F[b0:b0+128, i, :] @ Q_w^T  (K = 128, two 64-chunks) =====
    #pragma unroll 1
    for (int kc = 0; kc < 2; kc++) {
        __syncthreads();
        const float* Fb = F + ((size_t)b0 * NFLD + i) * DDIM + kc * 64;
        #pragma unroll
        for (int it = 0; it < 8; it++) {
            int x = tid + it * 256;
            int u = x >> 4, dq = (x & 15) << 2;
            float4 v = f2tf4(*reinterpret_cast<const float4*>(
                Fb + (size_t)u * NFLD * DDIM + dq));
            *reinterpret_cast<float4*>(As + u * AS_LD + dq) = v;
        }
        // Q_w chunk: Qs[e][dl] natural layout, ld 68 (conflict-free as col-frag)
        #pragma unroll
        for (int it = 0; it < 8; it++) {
            int x = tid + it * 256;            // 128 e x 64 dl = 8192 floats
            int e = x >> 4, dq = (x & 15) << 2;
            float4 v = f2tf4(*reinterpret_cast<const float4*>(
                Qw + e * DDIM + kc * 64 + dq));
            *reinterpret_cast<float4*>(Bs + e * BQ_LD + dq) = v;
        }
        __syncthreads();
        #pragma unroll
        for (int kk = 0; kk < 8; kk++) {
            const int k = kk * 8 + lc;
            unsigned a[4][4];
            #pragma unroll
            for (int mt = 0; mt < 4; mt++) {
                int r = wm * 64 + mt * 16 + lr;
                a[mt][0] = fb(As[r * AS_LD + k]);
                a[mt][1] = fb(As[(r + 8) * AS_LD + k]);
                a[mt][2] = fb(As[r * AS_LD + k + 4]);
                a[mt][3] = fb(As[(r + 8) * AS_LD + k + 4]);
            }
            #pragma unroll
            for (int nt = 0; nt < 4; nt++) {
                int n = wn * 32 + nt * 8 + lr;
                unsigned bb[2];
                bb[0] = fb(Bs[n * BQ_LD + k]);
                bb[1] = fb(Bs[n * BQ_LD + k + 4]);
                #pragma unroll
                for (int mt = 0; mt < 4; mt++) mma8(acc[mt][nt], a[mt], bb);
            }
        }
    }

    // ===== epilogue: stage n-halves through smem, coalesced float4 stores =====
    #pragma unroll 1
    for (int nh = 0; nh < 2; nh++) {
        __syncthreads();
        if ((wn >> 1) == nh) {
            #pragma unroll
            for (int mt = 0; mt < 4; mt++) {
                int r = wm * 64 + mt * 16 + lr;
                #pragma unroll
                for (int nt = 0; nt < 4; nt++) {
                    int cl = (wn & 1) * 32 + nt * 8 + 2 * lc;
                    As[r * AS_LD + cl]           = acc[mt][nt][0];
                    As[r * AS_LD + cl + 1]       = acc[mt][nt][1];
                    As[(r + 8) * AS_LD + cl]     = acc[mt][nt][2];
                    As[(r + 8) * AS_LD + cl + 1] = acc[mt][nt][3];
                }
            }
        }
        __syncthreads();
        #pragma unroll
        for (int it = 0; it < 8; it++) {
            int x = tid + it * 256;            // 128 x 64 / 4 = 2048 float4
            int u = x >> 4, cq = (x & 15) << 2;
            *reinterpret_cast<float4*>(
                out + ((size_t)(b0 + u) * NFLD + i) * DDIM + nh * 64 + cq) =
                *reinterpret_cast<const float4*>(As + u * AS_LD + cq);
        }
    }
}

// ---------------- launch ----------------
extern "C" void kernel_launch(void* const* d_in, const int* in_sizes, int n_in,
                              void* d_out, int out_size) {
    const float* F  = (const float*)d_in[0];
    const float* W  = (const float*)d_in[1];
    const float* Kw = (const float*)d_in[2];
    const float* Qw = (const float*)d_in[3];
    float* out = (float*)d_out;

    cudaFuncSetAttribute(k1_score, cudaFuncAttributeMaxDynamicSharedMemorySize, (int)K1_SMEM);
    cudaFuncSetAttribute(k2_out,   cudaFuncAttributeMaxDynamicSharedMemorySize, (int)K2_SMEM);

    k1_score<<<NB, 256, K1_SMEM>>>(F, Kw);
    dim3 g2(NB / 128, NFLD);
    k2_out<<<g2, 256, K2_SMEM>>>(F, W, Qw, out);
}

// round 9
// speedup vs baseline: 4.5363x; 1.6613x over previous
#include <cuda_runtime.h>
#include <cuda_fp16.h>
#include <cstdint>

#define NB   8192
#define NFLD 64
#define DDIM 128

// ---------------- device globals (no allocation allowed) ----------------
__device__ __align__(16) __half g_Sh [(size_t)NB * NFLD * NFLD];   // S fp16, 64 MB
__device__ __align__(16) __half g_Rh [(size_t)NB * NFLD * DDIM];   // R = F@Qw^T fp16, 128 MB
__device__ __align__(16) __half g_Wth[(size_t)NFLD * DDIM * NFLD]; // Wt[i][d][j] fp16
__device__ __align__(16) __half g_Kwh[DDIM * DDIM];                // fp16 K_w[e][d]
__device__ __align__(16) __half g_Qwh[DDIM * DDIM];                // fp16 Q_w[e][d]

// ---------------- helpers ----------------
__device__ __forceinline__ uint32_t smem_u32(const void* p) {
    uint32_t a;
    asm("{ .reg .u64 t; cvta.to.shared.u64 t, %1; cvt.u32.u64 %0, t; }"
        : "=r"(a) : "l"(p));
    return a;
}
__device__ __forceinline__ unsigned pk(float a, float b) {
    __half2 h = __floats2half2_rn(a, b);
    return *reinterpret_cast<unsigned*>(&h);
}
__device__ __forceinline__ uint4 cvt8(float4 a, float4 b) {
    return make_uint4(pk(a.x, a.y), pk(a.z, a.w), pk(b.x, b.y), pk(b.z, b.w));
}

// ldmatrix x4: loads 4 8x8 fp16 matrices, one 16B row address per lane
__device__ __forceinline__ void ldsm4(uint32_t* r, uint32_t addr) {
    asm volatile("ldmatrix.sync.aligned.m8n8.x4.shared.b16 {%0,%1,%2,%3}, [%4];"
                 : "=r"(r[0]), "=r"(r[1]), "=r"(r[2]), "=r"(r[3]) : "r"(addr));
}
// D += A*B : m16n8k16 fp16 in, f32 accum
__device__ __forceinline__ void mma16(float* c, const uint32_t* a, const uint32_t* b) {
    asm volatile("mma.sync.aligned.m16n8k16.row.col.f32.f16.f16.f32 "
                 "{%0,%1,%2,%3},{%4,%5,%6,%7},{%8,%9},{%0,%1,%2,%3};"
                 : "+f"(c[0]), "+f"(c[1]), "+f"(c[2]), "+f"(c[3])
                 : "r"(a[0]), "r"(a[1]), "r"(a[2]), "r"(a[3]), "r"(b[0]), "r"(b[1]));
}
// A-frag (16x16 tile at row0, half-col colh) from row-major fp16 smem, ld in halves
__device__ __forceinline__ uint32_t lda(uint32_t base, int ld, int row0, int colh, int lane) {
    return base + 2u * (uint32_t)((row0 + (lane & 15)) * ld + colh + ((lane >> 4) << 3));
}
// B-frags x4 (n16 x k16 at n0, k0) from row-major B^T[n][k] fp16 smem
__device__ __forceinline__ uint32_t ldb(uint32_t base, int ld, int n0, int k0, int lane) {
    int row  = n0 + ((lane >> 4) << 3) + (lane & 7);
    int koff = ((lane >> 3) & 1) << 3;
    return base + 2u * (uint32_t)(row * ld + k0 + koff);
}
// write a c-frag (4 f32) as fp16 pairs at (row,col) and (row+8,col)
__device__ __forceinline__ void dumph(char* smb, int ld, int row, int col, const float* c) {
    *reinterpret_cast<unsigned*>(smb + 2 * (row * ld + col))       = pk(c[0], c[1]);
    *reinterpret_cast<unsigned*>(smb + 2 * ((row + 8) * ld + col)) = pk(c[2], c[3]);
}

// ---------------- prep: fp16 weights + W transpose ----------------
__global__ void prep(const float* __restrict__ W, const float* __restrict__ Kw,
                     const float* __restrict__ Qw) {
    extern __shared__ __half th[];            // 64 x 136
    const int bid = blockIdx.x, tid = threadIdx.x;
    if (bid < 64) {
        const float4* W4 = reinterpret_cast<const float4*>(W) + (size_t)bid * 2048;
        #pragma unroll
        for (int it = 0; it < 8; it++) {
            int x = tid + it * 256;            // 0..2047
            float4 v = W4[x];
            int j = x >> 5, d4 = (x & 31) * 4;
            __half* p = th + j * 136 + d4;
            p[0] = __float2half_rn(v.x); p[1] = __float2half_rn(v.y);
            p[2] = __float2half_rn(v.z); p[3] = __float2half_rn(v.w);
        }
        __syncthreads();
        #pragma unroll
        for (int it = 0; it < 4; it++) {
            int x = tid + it * 256;            // d = x>>3, j8 = x&7
            int d = x >> 3, j0 = (x & 7) * 8;
            __half tmp[8];
            #pragma unroll
            for (int t = 0; t < 8; t++) tmp[t] = th[(j0 + t) * 136 + d];
            reinterpret_cast<uint4*>(g_Wth)[(size_t)bid * 1024 + x] =
                *reinterpret_cast<uint4*>(tmp);
        }
    } else {
        const float* src = (bid == 64) ? Kw : Qw;
        __half2* dst = reinterpret_cast<__half2*>((bid == 64) ? g_Kwh : g_Qwh);
        #pragma unroll
        for (int it = 0; it < 16; it++) {
            int x = tid + it * 256;            // 0..4095 float4
            float4 v = reinterpret_cast<const float4*>(src)[x];
            dst[2 * x]     = __floats2half2_rn(v.x, v.y);
            dst[2 * x + 1] = __floats2half2_rn(v.z, v.w);
        }
    }
}

// ---------------- k1: per 2 batches — Kf, S(diag), R ----------------
// smem: smF [128][136] fp16, smB [128][136] fp16 (Kw -> Qw -> R-stage),
//       smKf [128][136] fp16 (Kf -> S-stage [128][72])
#define K1_OFF_B  34816
#define K1_OFF_KF 69632
#define K1_SMEM   104448

__global__ void __launch_bounds__(256, 2) k1(const float* __restrict__ F) {
    extern __shared__ char sm[];
    char* smF  = sm;
    char* smB  = sm + K1_OFF_B;
    char* smKf = sm + K1_OFF_KF;
    const uint32_t ubF = smem_u32(smF), ubB = smem_u32(smB), ubKf = smem_u32(smKf);
    const int tid = threadIdx.x, wid = tid >> 5, lane = tid & 31;
    const int wm = wid >> 2, wn = wid & 3;
    const int r0 = lane >> 2, cO = 2 * (lane & 3);

    // ---- stage F2 (f32 -> fp16) and Kw ----
    {
        const float4* F4 = reinterpret_cast<const float4*>(F) + (size_t)blockIdx.x * 4096;
        #pragma unroll
        for (int it = 0; it < 8; it++) {
            int x = tid + it * 256;            // 0..2047 (uint4 of smem)
            int u = x >> 4, c8 = x & 15;
            float4 a = F4[u * 32 + c8 * 2], b = F4[u * 32 + c8 * 2 + 1];
            *reinterpret_cast<uint4*>(smF + 2 * (u * 136 + c8 * 8)) = cvt8(a, b);
            *reinterpret_cast<uint4*>(smB + 2 * (u * 136 + c8 * 8)) =
                reinterpret_cast<const uint4*>(g_Kwh)[x];
        }
    }
    __syncthreads();

    // ---- GEMM1: Kf = F2 @ Kw^T  (128x128, K=128) ----
    float accK[4][4][4];
    #pragma unroll
    for (int mt = 0; mt < 4; mt++)
        #pragma unroll
        for (int nt = 0; nt < 4; nt++)
            #pragma unroll
            for (int q = 0; q < 4; q++) accK[mt][nt][q] = 0.f;
    #pragma unroll
    for (int ks = 0; ks < 8; ks++) {
        uint32_t a[4][4], bq[2][4];
        #pragma unroll
        for (int mt = 0; mt < 4; mt++)
            ldsm4(a[mt], lda(ubF, 136, wm * 64 + mt * 16, ks * 16, lane));
        #pragma unroll
        for (int bt = 0; bt < 2; bt++)
            ldsm4(bq[bt], ldb(ubB, 136, wn * 32 + bt * 16, ks * 16, lane));
        #pragma unroll
        for (int mt = 0; mt < 4; mt++)
            #pragma unroll
            for (int nt = 0; nt < 4; nt++)
                mma16(accK[mt][nt], a[mt], &bq[nt >> 1][(nt & 1) * 2]);
    }
    __syncthreads();

    // ---- dump Kf -> smKf fp16; restage smB <- Qw ----
    #pragma unroll
    for (int mt = 0; mt < 4; mt++)
        #pragma unroll
        for (int nt = 0; nt < 4; nt++)
            dumph(smKf, 136, wm * 64 + mt * 16 + r0, wn * 32 + nt * 8 + cO, accK[mt][nt]);
    #pragma unroll
    for (int it = 0; it < 8; it++) {
        int x = tid + it * 256;
        *reinterpret_cast<uint4*>(smB + 2 * ((x >> 4) * 136 + (x & 15) * 8)) =
            reinterpret_cast<const uint4*>(g_Qwh)[x];
    }
    __syncthreads();

    // ---- GEMM2: S diag blocks (per batch 64x64, K=128) ----
    float accS[2][4][4];
    #pragma unroll
    for (int mt = 0; mt < 2; mt++)
        #pragma unroll
        for (int nt = 0; nt < 4; nt++)
            #pragma unroll
            for (int q = 0; q < 4; q++) accS[mt][nt][q] = 0.f;
    const int h = wid >> 2, ww = wid & 3;
    const int m0 = h * 64 + (ww & 1) * 32;         // A rows (i, batch-stacked)
    const int n0j = h * 64 + (ww >> 1) * 32;       // Kf rows (j, batch-stacked)
    #pragma unroll
    for (int ks = 0; ks < 8; ks++) {
        uint32_t a2[2][4], b2[2][4];
        #pragma unroll
        for (int mt = 0; mt < 2; mt++)
            ldsm4(a2[mt], lda(ubF, 136, m0 + mt * 16, ks * 16, lane));
        #pragma unroll
        for (int bt = 0; bt < 2; bt++)
            ldsm4(b2[bt], ldb(ubKf, 136, n0j + bt * 16, ks * 16, lane));
        #pragma unroll
        for (int mt = 0; mt < 2; mt++)
            #pragma unroll
            for (int nt = 0; nt < 4; nt++)
                mma16(accS[mt][nt], a2[mt], &b2[nt >> 1][(nt & 1) * 2]);
    }
    __syncthreads();

    // ---- dump S -> smKf reused as stage [128][72]; then GEMMR ----
    #pragma unroll
    for (int mt = 0; mt < 2; mt++)
        #pragma unroll
        for (int nt = 0; nt < 4; nt++)
            dumph(smKf, 72, m0 + mt * 16 + r0, (ww >> 1) * 32 + nt * 8 + cO, accS[mt][nt]);

    // GEMMR: R = F2 @ Qw^T (128x128, K=128) — reads smF/smB only
    float accR[4][4][4];
    #pragma unroll
    for (int mt = 0; mt < 4; mt++)
        #pragma unroll
        for (int nt = 0; nt < 4; nt++)
            #pragma unroll
            for (int q = 0; q < 4; q++) accR[mt][nt][q] = 0.f;
    #pragma unroll
    for (int ks = 0; ks < 8; ks++) {
        uint32_t a[4][4], bq[2][4];
        #pragma unroll
        for (int mt = 0; mt < 4; mt++)
            ldsm4(a[mt], lda(ubF, 136, wm * 64 + mt * 16, ks * 16, lane));
        #pragma unroll
        for (int bt = 0; bt < 2; bt++)
            ldsm4(bq[bt], ldb(ubB, 136, wn * 32 + bt * 16, ks * 16, lane));
        #pragma unroll
        for (int mt = 0; mt < 4; mt++)
            #pragma unroll
            for (int nt = 0; nt < 4; nt++)
                mma16(accR[mt][nt], a[mt], &bq[nt >> 1][(nt & 1) * 2]);
    }
    __syncthreads();

    // ---- bulk store S (reads smKf stage); dump R -> smB stage ----
    #pragma unroll
    for (int it = 0; it < 4; it++) {
        int x = tid + it * 256;                // 0..1023
        int bt = x >> 9, rem = x & 511, i = rem >> 3, c8 = rem & 7;
        uint4 v = *reinterpret_cast<const uint4*>(smKf + 2 * ((bt * 64 + i) * 72 + c8 * 8));
        reinterpret_cast<uint4*>(g_Sh)[(size_t)blockIdx.x * 1024 + bt * 512 + i * 8 + c8] = v;
    }
    #pragma unroll
    for (int mt = 0; mt < 4; mt++)
        #pragma unroll
        for (int nt = 0; nt < 4; nt++)
            dumph(smB, 136, wm * 64 + mt * 16 + r0, wn * 32 + nt * 8 + cO, accR[mt][nt]);
    __syncthreads();

    // ---- bulk store R ----
    #pragma unroll
    for (int it = 0; it < 8; it++) {
        int x = tid + it * 256;                // 0..2047
        uint4 v = *reinterpret_cast<const uint4*>(smB + 2 * ((x >> 4) * 136 + (x & 15) * 8));
        reinterpret_cast<uint4*>(g_Rh)[(size_t)blockIdx.x * 2048 + x] = v;
    }
}

// ---------------- k2: out[:,i,:] = S[:,i,:] @ Wt[i] + R[:,i,:] ----------------
// smem: smS [128][72], smW [128][72], smR [128][136]; epilogue Es f32 [128][68] @0
#define K2_OFF_W 18432
#define K2_OFF_R 36864
#define K2_SMEM  71680

__global__ void __launch_bounds__(256, 2) k2(float* __restrict__ out) {
    extern __shared__ char sm[];
    char* smS = sm;
    char* smW = sm + K2_OFF_W;
    char* smR = sm + K2_OFF_R;
    const uint32_t ubS = smem_u32(smS), ubW = smem_u32(smW);
    const int tid = threadIdx.x, wid = tid >> 5, lane = tid & 31;
    const int wm = wid >> 2, wn = wid & 3;
    const int r0 = lane >> 2, cO = 2 * (lane & 3);
    const int i = blockIdx.y;
    const int b0 = blockIdx.x * 128;

    // ---- stage S, Wt[i], R ----
    #pragma unroll
    for (int it = 0; it < 4; it++) {
        int x = tid + it * 256;                // 0..1023
        int u = x >> 3, c8 = x & 7;
        uint4 vs = reinterpret_cast<const uint4*>(g_Sh)[((size_t)(b0 + u) * NFLD + i) * 8 + c8];
        *reinterpret_cast<uint4*>(smS + 2 * (u * 72 + c8 * 8)) = vs;
        uint4 vw = reinterpret_cast<const uint4*>(g_Wth)[(size_t)i * 1024 + x];
        *reinterpret_cast<uint4*>(smW + 2 * (u * 72 + c8 * 8)) = vw;
    }
    #pragma unroll
    for (int it = 0; it < 8; it++) {
        int x = tid + it * 256;                // 0..2047
        int r = x >> 4, c8 = x & 15;
        uint4 v = reinterpret_cast<const uint4*>(g_Rh)[((size_t)(b0 + r) * NFLD + i) * 16 + c8];
        *reinterpret_cast<uint4*>(smR + 2 * (r * 136 + c8 * 8)) = v;
    }
    __syncthreads();

    // ---- GEMM: acc = S @ Wt[i]  (128x128, K=64) ----
    float acc[4][4][4];
    #pragma unroll
    for (int mt = 0; mt < 4; mt++)
        #pragma unroll
        for (int nt = 0; nt < 4; nt++)
            #pragma unroll
            for (int q = 0; q < 4; q++) acc[mt][nt][q] = 0.f;
    #pragma unroll
    for (int ks = 0; ks < 4; ks++) {
        uint32_t a[4][4], bq[2][4];
        #pragma unroll
        for (int mt = 0; mt < 4; mt++)
            ldsm4(a[mt], lda(ubS, 72, wm * 64 + mt * 16, ks * 16, lane));
        #pragma unroll
        for (int bt = 0; bt < 2; bt++)
            ldsm4(bq[bt], ldb(ubW, 72, wn * 32 + bt * 16, ks * 16, lane));
        #pragma unroll
        for (int mt = 0; mt < 4; mt++)
            #pragma unroll
            for (int nt = 0; nt < 4; nt++)
                mma16(acc[mt][nt], a[mt], &bq[nt >> 1][(nt & 1) * 2]);
    }

    // ---- add residual R from smem ----
    #pragma unroll
    for (int mt = 0; mt < 4; mt++) {
        int row = wm * 64 + mt * 16 + r0;
        #pragma unroll
        for (int nt = 0; nt < 4; nt++) {
            int col = wn * 32 + nt * 8 + cO;
            __half2 h0 = *reinterpret_cast<const __half2*>(smR + 2 * (row * 136 + col));
            __half2 h1 = *reinterpret_cast<const __half2*>(smR + 2 * ((row + 8) * 136 + col));
            float2 f0 = __half22float2(h0), f1 = __half22float2(h1);
            acc[mt][nt][0] += f0.x; acc[mt][nt][1] += f0.y;
            acc[mt][nt][2] += f1.x; acc[mt][nt][3] += f1.y;
        }
    }
    __syncthreads();

    // ---- epilogue: stage f32 halves, coalesced float4 stores ----
    float* Es = reinterpret_cast<float*>(sm);   // [128][68] f32 (over smS+smW)
    #pragma unroll 1
    for (int hh = 0; hh < 2; hh++) {
        if (hh) __syncthreads();
        if ((wn >> 1) == hh) {
            #pragma unroll
            for (int mt = 0; mt < 4; mt++) {
                int row = wm * 64 + mt * 16 + r0;
                #pragma unroll
                for (int nt = 0; nt < 4; nt++) {
                    int cl = (wn & 1) * 32 + nt * 8 + cO;
                    *reinterpret_cast<float2*>(Es + row * 68 + cl) =
                        make_float2(acc[mt][nt][0], acc[mt][nt][1]);
                    *reinterpret_cast<float2*>(Es + (row + 8) * 68 + cl) =
                        make_float2(acc[mt][nt][2], acc[mt][nt][3]);
                }
            }
        }
        __syncthreads();
        #pragma unroll
        for (int it = 0; it < 8; it++) {
            int x = tid + it * 256;            // 0..2047
            int u = x >> 4, c4 = x & 15;
            float4 v = *reinterpret_cast<const float4*>(Es + u * 68 + c4 * 4);
            *reinterpret_cast<float4*>(
                out + ((size_t)(b0 + u) * NFLD + i) * DDIM + hh * 64 + c4 * 4) = v;
        }
    }
}

// ---------------- launch ----------------
extern "C" void kernel_launch(void* const* d_in, const int* in_sizes, int n_in,
                              void* d_out, int out_size) {
    const float* F  = (const float*)d_in[0];
    const float* W  = (const float*)d_in[1];
    const float* Kw = (const float*)d_in[2];
    const float* Qw = (const float*)d_in[3];
    float* out = (float*)d_out;

    cudaFuncSetAttribute(prep, cudaFuncAttributeMaxDynamicSharedMemorySize, 17408);
    cudaFuncSetAttribute(k1,   cudaFuncAttributeMaxDynamicSharedMemorySize, K1_SMEM);
    cudaFuncSetAttribute(k2,   cudaFuncAttributeMaxDynamicSharedMemorySize, K2_SMEM);

    prep<<<66, 256, 17408>>>(W, Kw, Qw);
    k1<<<NB / 2, 256, K1_SMEM>>>(F);
    dim3 g2(NB / 128, NFLD);
    k2<<<g2, 256, K2_SMEM>>>(out);
}